// round 1
// baseline (speedup 1.0000x reference)
#include <cuda_runtime.h>
#include <cuda_bf16.h>

#define MAX_NODES 100000
#define FDIM 128

// Scratch (allocation-free rule: __device__ globals)
__device__ int   g_deg[MAX_NODES];
__device__ float g_dis[MAX_NODES];
__device__ float g_h[(size_t)MAX_NODES * FDIM];    // 51.2 MB
__device__ float g_agg[(size_t)MAX_NODES * FDIM];  // 51.2 MB

// ---------------- small utility kernels ----------------

__global__ void k_zero_deg(int n) {
    int i = blockIdx.x * blockDim.x + threadIdx.x;
    if (i < n) g_deg[i] = 0;
}

__global__ void k_count(const int* __restrict__ dst, int E) {
    int i = blockIdx.x * blockDim.x + threadIdx.x;
    if (i < E) atomicAdd(&g_deg[dst[i]], 1);
}

__global__ void k_dis(int n) {
    int i = blockIdx.x * blockDim.x + threadIdx.x;
    if (i < n) g_dis[i] = rsqrtf((float)(g_deg[i] + 1));  // +1 self-loop; always > 0
}

__global__ void k_zero_f4(float* __restrict__ p, int n4) {
    int i = blockIdx.x * blockDim.x + threadIdx.x;
    if (i < n4) ((float4*)p)[i] = make_float4(0.f, 0.f, 0.f, 0.f);
}

// ---------------- GEMM: H[N,128] = X[N,128] @ W[128,128] ----------------
// 256 threads/block, 64-row tile. W fully in SMEM (64KB) + X tile (64x129 padded).

__global__ void k_gemm(const float* __restrict__ X, const float* __restrict__ W,
                       float* __restrict__ H, int N)
{
    extern __shared__ float sm[];
    float* Ws = sm;              // 128*128
    float* Xs = sm + 128 * 128;  // 64*129 (pad to kill bank conflicts)

    int t = threadIdx.x;
    int row0 = blockIdx.x * 64;
    int rows = N - row0; if (rows > 64) rows = 64;

    // Load W (16384 floats = 4096 float4) coalesced
    const float4* W4 = (const float4*)W;
    float4* Ws4 = (float4*)Ws;
#pragma unroll
    for (int i = 0; i < 16; i++) Ws4[t + i * 256] = W4[t + i * 256];

    // Load X tile: 64 rows x 32 float4 = 2048 float4
    for (int i = t; i < 64 * 32; i += 256) {
        int r = i >> 5, c = i & 31;
        float4 v = (r < rows) ? ((const float4*)(X + (size_t)(row0 + r) * FDIM))[c]
                              : make_float4(0.f, 0.f, 0.f, 0.f);
        float* dp = Xs + r * 129 + c * 4;
        dp[0] = v.x; dp[1] = v.y; dp[2] = v.z; dp[3] = v.w;
    }
    __syncthreads();

    int tn = (t & 31) * 4;   // col base
    int tm = (t >> 5) * 8;   // row base within tile

    float acc[8][4];
#pragma unroll
    for (int i = 0; i < 8; i++)
#pragma unroll
        for (int j = 0; j < 4; j++) acc[i][j] = 0.f;

#pragma unroll 4
    for (int k = 0; k < 128; k++) {
        float4 b = *(const float4*)(Ws + k * 128 + tn);
#pragma unroll
        for (int i = 0; i < 8; i++) {
            float a = Xs[(tm + i) * 129 + k];
            acc[i][0] += a * b.x;
            acc[i][1] += a * b.y;
            acc[i][2] += a * b.z;
            acc[i][3] += a * b.w;
        }
    }

#pragma unroll
    for (int i = 0; i < 8; i++) {
        int r = tm + i;
        if (r < rows)
            *(float4*)(H + (size_t)(row0 + r) * FDIM + tn) =
                make_float4(acc[i][0], acc[i][1], acc[i][2], acc[i][3]);
    }
}

// ---------------- edge scatter: agg[dst] += h[src] * dis[src]*dis[dst] ----------------
// One warp per edge; each lane handles one float4 (4 of the 128 features).
// Vectorized reduction (red.global.add.v4.f32) -> 4x fewer atomic ops.

__global__ void k_scatter(const int* __restrict__ src, const int* __restrict__ dst,
                          const float* __restrict__ h, float* __restrict__ agg, int E)
{
    int lane = threadIdx.x & 31;
    int w = (blockIdx.x * blockDim.x + threadIdx.x) >> 5;
    if (w >= E) return;

    int s = 0, d = 0;
    float nw = 0.f;
    if (lane == 0) {
        s = src[w];
        d = dst[w];
        nw = g_dis[s] * g_dis[d];
    }
    s  = __shfl_sync(0xffffffff, s, 0);
    d  = __shfl_sync(0xffffffff, d, 0);
    nw = __shfl_sync(0xffffffff, nw, 0);

    float4 v = ((const float4*)(h + (size_t)s * FDIM))[lane];
    float* ap = agg + (size_t)d * FDIM + lane * 4;
    asm volatile("red.global.add.v4.f32 [%0], {%1, %2, %3, %4};"
                 :: "l"(ap), "f"(v.x * nw), "f"(v.y * nw), "f"(v.z * nw), "f"(v.w * nw)
                 : "memory");
}

// ---------------- finalize: out = act(agg + h*dis^2 + b) ----------------
// Handles the self-loop term (norm = dis[i]^2) + bias + optional ReLU. In-place safe.

__global__ void k_finalize(const float* __restrict__ agg, const float* __restrict__ h,
                           const float* __restrict__ b, float* __restrict__ out,
                           int N, int doRelu)
{
    int idx = blockIdx.x * blockDim.x + threadIdx.x;  // over N*32 float4s
    if (idx >= N * 32) return;
    int node = idx >> 5;
    int c4 = idx & 31;
    float ds = g_dis[node];
    float d2 = ds * ds;
    float4 a  = ((const float4*)agg)[idx];
    float4 hv = ((const float4*)h)[idx];
    float4 bv = ((const float4*)b)[c4];
    float4 o;
    o.x = a.x + hv.x * d2 + bv.x;
    o.y = a.y + hv.y * d2 + bv.y;
    o.z = a.z + hv.z * d2 + bv.z;
    o.w = a.w + hv.w * d2 + bv.w;
    if (doRelu) {
        o.x = fmaxf(o.x, 0.f); o.y = fmaxf(o.y, 0.f);
        o.z = fmaxf(o.z, 0.f); o.w = fmaxf(o.w, 0.f);
    }
    ((float4*)out)[idx] = o;
}

// ---------------- launch ----------------

extern "C" void kernel_launch(void* const* d_in, const int* in_sizes, int n_in,
                              void* d_out, int out_size)
{
    // Inputs: 0 edge_index [2,E] (int32), 1 edge_attr (unused), 2 emb [N,128],
    //         3 W1 [128,128], 4 b1 [128], 5 W2 [128,128], 6 b2 [128]
    const int*   eidx = (const int*)d_in[0];
    const float* emb  = (const float*)d_in[2];
    const float* W1   = (const float*)d_in[3];
    const float* b1   = (const float*)d_in[4];
    const float* W2   = (const float*)d_in[5];
    const float* b2   = (const float*)d_in[6];
    float* out = (float*)d_out;

    const int E = in_sizes[0] / 2;
    const int N = in_sizes[2] / FDIM;
    const int* src = eidx;
    const int* dst = eidx + E;

    static bool attr_set = false;
    const int GEMM_SMEM = (128 * 128 + 64 * 129) * (int)sizeof(float);  // 98560 B
    cudaFuncSetAttribute(k_gemm, cudaFuncAttributeMaxDynamicSharedMemorySize, GEMM_SMEM);
    (void)attr_set;

    float* hbuf;   cudaGetSymbolAddress((void**)&hbuf, g_h);
    float* abuf;   cudaGetSymbolAddress((void**)&abuf, g_agg);

    const int n4 = N * (FDIM / 4);           // float4 count per feature matrix
    const int zb = (n4 + 255) / 256;
    const int nb = (N + 255) / 256;
    const int eb = (E + 255) / 256;
    const int gemmBlocks = (N + 63) / 64;
    const int scatterBlocks = (E * 32 + 255) / 256;  // 1 warp/edge

    // degrees -> dis
    k_zero_deg<<<nb, 256>>>(N);
    k_count<<<eb, 256>>>(dst, E);
    k_dis<<<nb, 256>>>(N);

    // ---- layer 1 ----
    k_zero_f4<<<zb, 256>>>(abuf, n4);
    k_gemm<<<gemmBlocks, 256, GEMM_SMEM>>>(emb, W1, hbuf, N);
    k_scatter<<<scatterBlocks, 256>>>(src, dst, hbuf, abuf, E);
    k_finalize<<<zb, 256>>>(abuf, hbuf, b1, abuf, N, 1);   // in-place, ReLU

    // ---- layer 2 ----
    k_gemm<<<gemmBlocks, 256, GEMM_SMEM>>>(abuf, W2, hbuf, N);
    k_zero_f4<<<zb, 256>>>(out, n4);
    k_scatter<<<scatterBlocks, 256>>>(src, dst, hbuf, out, E);
    k_finalize<<<zb, 256>>>(out, hbuf, b2, out, N, 0);     // no ReLU
}

// round 2
// speedup vs baseline: 1.2601x; 1.2601x over previous
#include <cuda_runtime.h>
#include <cuda_bf16.h>

#define MAX_NODES 100000
#define MAX_EDGES 1600000
#define FDIM 128

// Scratch (allocation-free rule: __device__ globals)
__device__ int   g_deg[MAX_NODES];
__device__ float g_dis[MAX_NODES];
__device__ int   g_rowptr[MAX_NODES + 1];
__device__ int   g_fill[MAX_NODES];
__device__ int   g_csr[MAX_EDGES];                 // src ids sorted by dst
__device__ float g_h[(size_t)MAX_NODES * FDIM];    // 51.2 MB
__device__ float g_agg[(size_t)MAX_NODES * FDIM];  // 51.2 MB

// ---------------- CSR build ----------------

__global__ void k_zero_deg(int n) {
    int i = blockIdx.x * blockDim.x + threadIdx.x;
    if (i < n) g_deg[i] = 0;
}

__global__ void k_count(const int* __restrict__ dst, int E) {
    int i = blockIdx.x * blockDim.x + threadIdx.x;
    if (i < E) atomicAdd(&g_deg[dst[i]], 1);
}

__global__ void k_dis(int n) {
    int i = blockIdx.x * blockDim.x + threadIdx.x;
    if (i < n) g_dis[i] = rsqrtf((float)(g_deg[i] + 1));  // +1 self-loop
}

// Single-block exclusive scan of g_deg -> g_rowptr (+ copy to g_fill).
__global__ void k_scan(int N) {
    __shared__ int ssum[1024];
    int t = threadIdx.x;
    int chunk = (N + 1023) / 1024;
    int lo = t * chunk, hi = lo + chunk; if (hi > N) hi = N; if (lo > N) lo = N;
    int s = 0;
    for (int i = lo; i < hi; i++) s += g_deg[i];
    ssum[t] = s;
    __syncthreads();
    for (int off = 1; off < 1024; off <<= 1) {
        int v = (t >= off) ? ssum[t - off] : 0;
        __syncthreads();
        ssum[t] += v;
        __syncthreads();
    }
    int run = t ? ssum[t - 1] : 0;
    for (int i = lo; i < hi; i++) {
        int d = g_deg[i];
        g_rowptr[i] = run;
        g_fill[i]   = run;
        run += d;
    }
    if (t == 1023) g_rowptr[N] = ssum[1023];
}

__global__ void k_fill(const int* __restrict__ src, const int* __restrict__ dst, int E) {
    int i = blockIdx.x * blockDim.x + threadIdx.x;
    if (i < E) {
        int p = atomicAdd(&g_fill[dst[i]], 1);
        g_csr[p] = src[i];
    }
}

// ---------------- GEMM: H[N,128] = X[N,128] @ W[128,128] ----------------

__global__ void k_gemm(const float* __restrict__ X, const float* __restrict__ W,
                       float* __restrict__ H, int N)
{
    extern __shared__ float sm[];
    float* Ws = sm;              // 128*128
    float* Xs = sm + 128 * 128;  // 64*129 padded

    int t = threadIdx.x;
    int row0 = blockIdx.x * 64;
    int rows = N - row0; if (rows > 64) rows = 64;

    const float4* W4 = (const float4*)W;
    float4* Ws4 = (float4*)Ws;
#pragma unroll
    for (int i = 0; i < 16; i++) Ws4[t + i * 256] = W4[t + i * 256];

    for (int i = t; i < 64 * 32; i += 256) {
        int r = i >> 5, c = i & 31;
        float4 v = (r < rows) ? ((const float4*)(X + (size_t)(row0 + r) * FDIM))[c]
                              : make_float4(0.f, 0.f, 0.f, 0.f);
        float* dp = Xs + r * 129 + c * 4;
        dp[0] = v.x; dp[1] = v.y; dp[2] = v.z; dp[3] = v.w;
    }
    __syncthreads();

    int tn = (t & 31) * 4;
    int tm = (t >> 5) * 8;

    float acc[8][4];
#pragma unroll
    for (int i = 0; i < 8; i++)
#pragma unroll
        for (int j = 0; j < 4; j++) acc[i][j] = 0.f;

#pragma unroll 4
    for (int k = 0; k < 128; k++) {
        float4 b = *(const float4*)(Ws + k * 128 + tn);
#pragma unroll
        for (int i = 0; i < 8; i++) {
            float a = Xs[(tm + i) * 129 + k];
            acc[i][0] += a * b.x;
            acc[i][1] += a * b.y;
            acc[i][2] += a * b.z;
            acc[i][3] += a * b.w;
        }
    }

#pragma unroll
    for (int i = 0; i < 8; i++) {
        int r = tm + i;
        if (r < rows)
            *(float4*)(H + (size_t)(row0 + r) * FDIM + tn) =
                make_float4(acc[i][0], acc[i][1], acc[i][2], acc[i][3]);
    }
}

// ---------------- CSR aggregate + fused epilogue ----------------
// One warp per dst node; each lane owns one float4 (4 features).
// out[v] = act( dis[v] * sum_{s in N(v)} dis[s]*h[s]  +  dis[v]^2 * h[v]  +  b )

__global__ void k_aggregate(const float* __restrict__ h, const float* __restrict__ bias,
                            float* __restrict__ out, int N, int doRelu)
{
    int lane = threadIdx.x & 31;
    int v = (blockIdx.x * blockDim.x + threadIdx.x) >> 5;
    if (v >= N) return;

    int b0 = g_rowptr[v];
    int b1 = g_rowptr[v + 1];
    const float4* h4 = (const float4*)h;

    float4 a0 = make_float4(0.f, 0.f, 0.f, 0.f);
    float4 a1 = a0, a2 = a0, a3 = a0;

    int e = b0;
    for (; e + 4 <= b1; e += 4) {
        int s0 = g_csr[e], s1 = g_csr[e + 1], s2 = g_csr[e + 2], s3 = g_csr[e + 3];
        float w0 = g_dis[s0], w1 = g_dis[s1], w2 = g_dis[s2], w3 = g_dis[s3];
        float4 v0 = h4[(size_t)s0 * 32 + lane];
        float4 v1 = h4[(size_t)s1 * 32 + lane];
        float4 v2 = h4[(size_t)s2 * 32 + lane];
        float4 v3 = h4[(size_t)s3 * 32 + lane];
        a0.x += w0 * v0.x; a0.y += w0 * v0.y; a0.z += w0 * v0.z; a0.w += w0 * v0.w;
        a1.x += w1 * v1.x; a1.y += w1 * v1.y; a1.z += w1 * v1.z; a1.w += w1 * v1.w;
        a2.x += w2 * v2.x; a2.y += w2 * v2.y; a2.z += w2 * v2.z; a2.w += w2 * v2.w;
        a3.x += w3 * v3.x; a3.y += w3 * v3.y; a3.z += w3 * v3.z; a3.w += w3 * v3.w;
    }
    for (; e < b1; e++) {
        int s0 = g_csr[e];
        float w0 = g_dis[s0];
        float4 v0 = h4[(size_t)s0 * 32 + lane];
        a0.x += w0 * v0.x; a0.y += w0 * v0.y; a0.z += w0 * v0.z; a0.w += w0 * v0.w;
    }

    a0.x += a1.x + a2.x + a3.x;
    a0.y += a1.y + a2.y + a3.y;
    a0.z += a1.z + a2.z + a3.z;
    a0.w += a1.w + a2.w + a3.w;

    float dv = g_dis[v];
    float d2 = dv * dv;
    float4 hv = h4[(size_t)v * 32 + lane];
    float4 bv = ((const float4*)bias)[lane];

    float4 o;
    o.x = dv * a0.x + d2 * hv.x + bv.x;
    o.y = dv * a0.y + d2 * hv.y + bv.y;
    o.z = dv * a0.z + d2 * hv.z + bv.z;
    o.w = dv * a0.w + d2 * hv.w + bv.w;
    if (doRelu) {
        o.x = fmaxf(o.x, 0.f); o.y = fmaxf(o.y, 0.f);
        o.z = fmaxf(o.z, 0.f); o.w = fmaxf(o.w, 0.f);
    }
    ((float4*)out)[(size_t)v * 32 + lane] = o;
}

// ---------------- launch ----------------

extern "C" void kernel_launch(void* const* d_in, const int* in_sizes, int n_in,
                              void* d_out, int out_size)
{
    const int*   eidx = (const int*)d_in[0];
    const float* emb  = (const float*)d_in[2];
    const float* W1   = (const float*)d_in[3];
    const float* b1   = (const float*)d_in[4];
    const float* W2   = (const float*)d_in[5];
    const float* b2   = (const float*)d_in[6];
    float* out = (float*)d_out;

    const int E = in_sizes[0] / 2;
    const int N = in_sizes[2] / FDIM;
    const int* src = eidx;
    const int* dst = eidx + E;

    const int GEMM_SMEM = (128 * 128 + 64 * 129) * (int)sizeof(float);  // 98560 B
    cudaFuncSetAttribute(k_gemm, cudaFuncAttributeMaxDynamicSharedMemorySize, GEMM_SMEM);

    float* hbuf; cudaGetSymbolAddress((void**)&hbuf, g_h);
    float* abuf; cudaGetSymbolAddress((void**)&abuf, g_agg);

    const int nb = (N + 255) / 256;
    const int eb = (E + 255) / 256;
    const int gemmBlocks = (N + 63) / 64;
    const int aggBlocks = (N * 32 + 255) / 256;  // 1 warp/node

    // CSR build (by dst) + norms
    k_zero_deg<<<nb, 256>>>(N);
    k_count<<<eb, 256>>>(dst, E);
    k_dis<<<nb, 256>>>(N);
    k_scan<<<1, 1024>>>(N);
    k_fill<<<eb, 256>>>(src, dst, E);

    // ---- layer 1 ----
    k_gemm<<<gemmBlocks, 256, GEMM_SMEM>>>(emb, W1, hbuf, N);
    k_aggregate<<<aggBlocks, 256>>>(hbuf, b1, abuf, N, 1);

    // ---- layer 2 ----
    k_gemm<<<gemmBlocks, 256, GEMM_SMEM>>>(abuf, W2, hbuf, N);
    k_aggregate<<<aggBlocks, 256>>>(hbuf, b2, out, N, 0);
}

// round 3
// speedup vs baseline: 1.2651x; 1.0040x over previous
#include <cuda_runtime.h>
#include <cuda_bf16.h>

#define MAX_NODES 100000
#define MAX_EDGES 1600000
#define FDIM 128

// Scratch (allocation-free rule: __device__ globals)
__device__ int   g_deg[MAX_NODES];
__device__ float g_dis[MAX_NODES];
__device__ int   g_rowptr[MAX_NODES + 1];
__device__ int   g_fill[MAX_NODES];
__device__ int   g_csr[MAX_EDGES];                 // src ids sorted by dst
__device__ float g_h[(size_t)MAX_NODES * FDIM];    // 51.2 MB
__device__ float g_agg[(size_t)MAX_NODES * FDIM];  // 51.2 MB

// ---------------- CSR build ----------------

__global__ void k_zero_deg(int n) {
    int i = blockIdx.x * blockDim.x + threadIdx.x;
    if (i < n) g_deg[i] = 0;
}

__global__ void k_count(const int* __restrict__ dst, int E) {
    int i = blockIdx.x * blockDim.x + threadIdx.x;
    if (i < E) atomicAdd(&g_deg[dst[i]], 1);
}

__global__ void k_dis(int n) {
    int i = blockIdx.x * blockDim.x + threadIdx.x;
    if (i < n) g_dis[i] = rsqrtf((float)(g_deg[i] + 1));  // +1 self-loop
}

// Single-block exclusive scan of g_deg -> g_rowptr (+ copy to g_fill).
__global__ void k_scan(int N) {
    __shared__ int ssum[1024];
    int t = threadIdx.x;
    int chunk = (N + 1023) / 1024;
    int lo = t * chunk, hi = lo + chunk; if (hi > N) hi = N; if (lo > N) lo = N;
    int s = 0;
    for (int i = lo; i < hi; i++) s += g_deg[i];
    ssum[t] = s;
    __syncthreads();
    for (int off = 1; off < 1024; off <<= 1) {
        int v = (t >= off) ? ssum[t - off] : 0;
        __syncthreads();
        ssum[t] += v;
        __syncthreads();
    }
    int run = t ? ssum[t - 1] : 0;
    for (int i = lo; i < hi; i++) {
        int d = g_deg[i];
        g_rowptr[i] = run;
        g_fill[i]   = run;
        run += d;
    }
    if (t == 1023) g_rowptr[N] = ssum[1023];
}

__global__ void k_fill(const int* __restrict__ src, const int* __restrict__ dst, int E) {
    int i = blockIdx.x * blockDim.x + threadIdx.x;
    if (i < E) {
        int p = atomicAdd(&g_fill[dst[i]], 1);
        g_csr[p] = src[i];
    }
}

// ---------------- GEMM: H[N,128] = X[N,128] @ W[128,128] ----------------

__global__ void k_gemm(const float* __restrict__ X, const float* __restrict__ W,
                       float* __restrict__ H, int N)
{
    extern __shared__ float sm[];
    float* Ws = sm;              // 128*128
    float* Xs = sm + 128 * 128;  // 64*129 padded

    int t = threadIdx.x;
    int row0 = blockIdx.x * 64;
    int rows = N - row0; if (rows > 64) rows = 64;

    const float4* W4 = (const float4*)W;
    float4* Ws4 = (float4*)Ws;
#pragma unroll
    for (int i = 0; i < 16; i++) Ws4[t + i * 256] = W4[t + i * 256];

    for (int i = t; i < 64 * 32; i += 256) {
        int r = i >> 5, c = i & 31;
        float4 v = (r < rows) ? ((const float4*)(X + (size_t)(row0 + r) * FDIM))[c]
                              : make_float4(0.f, 0.f, 0.f, 0.f);
        float* dp = Xs + r * 129 + c * 4;
        dp[0] = v.x; dp[1] = v.y; dp[2] = v.z; dp[3] = v.w;
    }
    __syncthreads();

    int tn = (t & 31) * 4;
    int tm = (t >> 5) * 8;

    float acc[8][4];
#pragma unroll
    for (int i = 0; i < 8; i++)
#pragma unroll
        for (int j = 0; j < 4; j++) acc[i][j] = 0.f;

#pragma unroll 4
    for (int k = 0; k < 128; k++) {
        float4 b = *(const float4*)(Ws + k * 128 + tn);
#pragma unroll
        for (int i = 0; i < 8; i++) {
            float a = Xs[(tm + i) * 129 + k];
            acc[i][0] += a * b.x;
            acc[i][1] += a * b.y;
            acc[i][2] += a * b.z;
            acc[i][3] += a * b.w;
        }
    }

#pragma unroll
    for (int i = 0; i < 8; i++) {
        int r = tm + i;
        if (r < rows)
            *(float4*)(H + (size_t)(row0 + r) * FDIM + tn) =
                make_float4(acc[i][0], acc[i][1], acc[i][2], acc[i][3]);
    }
}

// ---------------- CSR aggregate + fused epilogue ----------------
// One warp per dst node; each lane owns one float4 (4 features).
// out[v] = act( dis[v] * sum_{s in N(v)} dis[s]*h[s]  +  dis[v]^2 * h[v]  +  b )

__global__ void k_aggregate(const float* __restrict__ h, const float* __restrict__ bias,
                            float* __restrict__ out, int N, int doRelu)
{
    int lane = threadIdx.x & 31;
    int v = (blockIdx.x * blockDim.x + threadIdx.x) >> 5;
    if (v >= N) return;

    int b0 = g_rowptr[v];
    int b1 = g_rowptr[v + 1];
    const float4* h4 = (const float4*)h;

    float4 a0 = make_float4(0.f, 0.f, 0.f, 0.f);
    float4 a1 = a0, a2 = a0, a3 = a0;

    int e = b0;
    for (; e + 4 <= b1; e += 4) {
        int s0 = g_csr[e], s1 = g_csr[e + 1], s2 = g_csr[e + 2], s3 = g_csr[e + 3];
        float w0 = g_dis[s0], w1 = g_dis[s1], w2 = g_dis[s2], w3 = g_dis[s3];
        float4 v0 = h4[(size_t)s0 * 32 + lane];
        float4 v1 = h4[(size_t)s1 * 32 + lane];
        float4 v2 = h4[(size_t)s2 * 32 + lane];
        float4 v3 = h4[(size_t)s3 * 32 + lane];
        a0.x += w0 * v0.x; a0.y += w0 * v0.y; a0.z += w0 * v0.z; a0.w += w0 * v0.w;
        a1.x += w1 * v1.x; a1.y += w1 * v1.y; a1.z += w1 * v1.z; a1.w += w1 * v1.w;
        a2.x += w2 * v2.x; a2.y += w2 * v2.y; a2.z += w2 * v2.z; a2.w += w2 * v2.w;
        a3.x += w3 * v3.x; a3.y += w3 * v3.y; a3.z += w3 * v3.z; a3.w += w3 * v3.w;
    }
    for (; e < b1; e++) {
        int s0 = g_csr[e];
        float w0 = g_dis[s0];
        float4 v0 = h4[(size_t)s0 * 32 + lane];
        a0.x += w0 * v0.x; a0.y += w0 * v0.y; a0.z += w0 * v0.z; a0.w += w0 * v0.w;
    }

    a0.x += a1.x + a2.x + a3.x;
    a0.y += a1.y + a2.y + a3.y;
    a0.z += a1.z + a2.z + a3.z;
    a0.w += a1.w + a2.w + a3.w;

    float dv = g_dis[v];
    float d2 = dv * dv;
    float4 hv = h4[(size_t)v * 32 + lane];
    float4 bv = ((const float4*)bias)[lane];

    float4 o;
    o.x = dv * a0.x + d2 * hv.x + bv.x;
    o.y = dv * a0.y + d2 * hv.y + bv.y;
    o.z = dv * a0.z + d2 * hv.z + bv.z;
    o.w = dv * a0.w + d2 * hv.w + bv.w;
    if (doRelu) {
        o.x = fmaxf(o.x, 0.f); o.y = fmaxf(o.y, 0.f);
        o.z = fmaxf(o.z, 0.f); o.w = fmaxf(o.w, 0.f);
    }
    ((float4*)out)[(size_t)v * 32 + lane] = o;
}

// ---------------- launch ----------------

extern "C" void kernel_launch(void* const* d_in, const int* in_sizes, int n_in,
                              void* d_out, int out_size)
{
    const int*   eidx = (const int*)d_in[0];
    const float* emb  = (const float*)d_in[2];
    const float* W1   = (const float*)d_in[3];
    const float* b1   = (const float*)d_in[4];
    const float* W2   = (const float*)d_in[5];
    const float* b2   = (const float*)d_in[6];
    float* out = (float*)d_out;

    const int E = in_sizes[0] / 2;
    const int N = in_sizes[2] / FDIM;
    const int* src = eidx;
    const int* dst = eidx + E;

    const int GEMM_SMEM = (128 * 128 + 64 * 129) * (int)sizeof(float);  // 98560 B
    cudaFuncSetAttribute(k_gemm, cudaFuncAttributeMaxDynamicSharedMemorySize, GEMM_SMEM);

    float* hbuf; cudaGetSymbolAddress((void**)&hbuf, g_h);
    float* abuf; cudaGetSymbolAddress((void**)&abuf, g_agg);

    const int nb = (N + 255) / 256;
    const int eb = (E + 255) / 256;
    const int gemmBlocks = (N + 63) / 64;
    const int aggBlocks = (N * 32 + 255) / 256;  // 1 warp/node

    // CSR build (by dst) + norms
    k_zero_deg<<<nb, 256>>>(N);
    k_count<<<eb, 256>>>(dst, E);
    k_dis<<<nb, 256>>>(N);
    k_scan<<<1, 1024>>>(N);
    k_fill<<<eb, 256>>>(src, dst, E);

    // ---- layer 1 ----
    k_gemm<<<gemmBlocks, 256, GEMM_SMEM>>>(emb, W1, hbuf, N);
    k_aggregate<<<aggBlocks, 256>>>(hbuf, b1, abuf, N, 1);

    // ---- layer 2 ----
    k_gemm<<<gemmBlocks, 256, GEMM_SMEM>>>(abuf, W2, hbuf, N);
    k_aggregate<<<aggBlocks, 256>>>(hbuf, b2, out, N, 0);
}

// round 4
// speedup vs baseline: 1.8018x; 1.4242x over previous
#include <cuda_runtime.h>
#include <cuda_bf16.h>

#define MAX_NODES 100000
#define MAX_EDGES 1600000
#define FDIM 128
#define SCAN_B 256
#define MAX_BLOCKS ((MAX_NODES + SCAN_B - 1) / SCAN_B)   // 391

// Scratch (allocation-free rule: __device__ globals)
__device__ int   g_deg[MAX_NODES];
__device__ float g_dis[MAX_NODES];
__device__ int   g_rowptr[MAX_NODES + 1];
__device__ int   g_fill[MAX_NODES];
__device__ int   g_bsum[MAX_BLOCKS];
__device__ int   g_csr[MAX_EDGES];                 // src ids sorted by dst
__device__ float g_h[(size_t)MAX_NODES * FDIM];    // 51.2 MB
__device__ float g_agg[(size_t)MAX_NODES * FDIM];  // 51.2 MB

// ---------------- CSR build ----------------

__global__ void k_zero_deg(int n) {
    int i = blockIdx.x * blockDim.x + threadIdx.x;
    if (i < n) g_deg[i] = 0;
}

__global__ void k_count(const int* __restrict__ dst, int E) {
    int i = blockIdx.x * blockDim.x + threadIdx.x;
    if (i < E) atomicAdd(&g_deg[dst[i]], 1);
}

__global__ void k_dis(int n) {
    int i = blockIdx.x * blockDim.x + threadIdx.x;
    if (i < n) g_dis[i] = rsqrtf((float)(g_deg[i] + 1));  // +1 self-loop
}

// Phase 1: per-block sum of degrees
__global__ void k_blocksum(int N) {
    __shared__ int s[SCAN_B];
    int i = blockIdx.x * SCAN_B + threadIdx.x;
    s[threadIdx.x] = (i < N) ? g_deg[i] : 0;
    __syncthreads();
#pragma unroll
    for (int off = SCAN_B / 2; off > 0; off >>= 1) {
        if (threadIdx.x < off) s[threadIdx.x] += s[threadIdx.x + off];
        __syncthreads();
    }
    if (threadIdx.x == 0) g_bsum[blockIdx.x] = s[0];
}

// Phase 2: single-block exclusive scan of block sums (nb <= 1024)
__global__ void k_scanbsums(int nb, int N) {
    __shared__ int s[1024];
    int t = threadIdx.x;
    int v = (t < nb) ? g_bsum[t] : 0;
    s[t] = v;
    __syncthreads();
    for (int off = 1; off < 1024; off <<= 1) {
        int u = (t >= off) ? s[t - off] : 0;
        __syncthreads();
        s[t] += u;
        __syncthreads();
    }
    if (t < nb) g_bsum[t] = s[t] - v;          // exclusive
    if (t == nb - 1) g_rowptr[N] = s[t];       // total edge count
}

// Phase 3: block-local exclusive scan + block offset -> rowptr/fill
__global__ void k_rowptr(int N) {
    __shared__ int s[SCAN_B];
    int i = blockIdx.x * SCAN_B + threadIdx.x;
    int t = threadIdx.x;
    int d = (i < N) ? g_deg[i] : 0;
    s[t] = d;
    __syncthreads();
#pragma unroll
    for (int off = 1; off < SCAN_B; off <<= 1) {
        int u = (t >= off) ? s[t - off] : 0;
        __syncthreads();
        s[t] += u;
        __syncthreads();
    }
    if (i < N) {
        int p = g_bsum[blockIdx.x] + s[t] - d;  // exclusive position
        g_rowptr[i] = p;
        g_fill[i]   = p;
    }
}

__global__ void k_fill(const int* __restrict__ src, const int* __restrict__ dst, int E) {
    int i = blockIdx.x * blockDim.x + threadIdx.x;
    if (i < E) {
        int p = atomicAdd(&g_fill[dst[i]], 1);
        g_csr[p] = src[i];
    }
}

// ---------------- GEMM: H[N,128] = X[N,128] @ W[128,128] ----------------

__global__ void k_gemm(const float* __restrict__ X, const float* __restrict__ W,
                       float* __restrict__ H, int N)
{
    extern __shared__ float sm[];
    float* Ws = sm;              // 128*128
    float* Xs = sm + 128 * 128;  // 64*129 padded

    int t = threadIdx.x;
    int row0 = blockIdx.x * 64;
    int rows = N - row0; if (rows > 64) rows = 64;

    const float4* W4 = (const float4*)W;
    float4* Ws4 = (float4*)Ws;
#pragma unroll
    for (int i = 0; i < 16; i++) Ws4[t + i * 256] = W4[t + i * 256];

    for (int i = t; i < 64 * 32; i += 256) {
        int r = i >> 5, c = i & 31;
        float4 v = (r < rows) ? ((const float4*)(X + (size_t)(row0 + r) * FDIM))[c]
                              : make_float4(0.f, 0.f, 0.f, 0.f);
        float* dp = Xs + r * 129 + c * 4;
        dp[0] = v.x; dp[1] = v.y; dp[2] = v.z; dp[3] = v.w;
    }
    __syncthreads();

    int tn = (t & 31) * 4;
    int tm = (t >> 5) * 8;

    float acc[8][4];
#pragma unroll
    for (int i = 0; i < 8; i++)
#pragma unroll
        for (int j = 0; j < 4; j++) acc[i][j] = 0.f;

#pragma unroll 4
    for (int k = 0; k < 128; k++) {
        float4 b = *(const float4*)(Ws + k * 128 + tn);
#pragma unroll
        for (int i = 0; i < 8; i++) {
            float a = Xs[(tm + i) * 129 + k];
            acc[i][0] += a * b.x;
            acc[i][1] += a * b.y;
            acc[i][2] += a * b.z;
            acc[i][3] += a * b.w;
        }
    }

#pragma unroll
    for (int i = 0; i < 8; i++) {
        int r = tm + i;
        if (r < rows)
            *(float4*)(H + (size_t)(row0 + r) * FDIM + tn) =
                make_float4(acc[i][0], acc[i][1], acc[i][2], acc[i][3]);
    }
}

// ---------------- CSR aggregate + fused epilogue ----------------
// One warp per dst node; each lane owns one float4 (4 features).
// out[v] = act( dis[v] * sum_{s in N(v)} dis[s]*h[s]  +  dis[v]^2 * h[v]  +  b )

__global__ void k_aggregate(const float* __restrict__ h, const float* __restrict__ bias,
                            float* __restrict__ out, int N, int doRelu)
{
    int lane = threadIdx.x & 31;
    int v = (blockIdx.x * blockDim.x + threadIdx.x) >> 5;
    if (v >= N) return;

    int b0 = g_rowptr[v];
    int b1 = g_rowptr[v + 1];
    const float4* h4 = (const float4*)h;

    float4 a0 = make_float4(0.f, 0.f, 0.f, 0.f);
    float4 a1 = a0, a2 = a0, a3 = a0;

    int e = b0;
    for (; e + 4 <= b1; e += 4) {
        int s0 = g_csr[e], s1 = g_csr[e + 1], s2 = g_csr[e + 2], s3 = g_csr[e + 3];
        float w0 = g_dis[s0], w1 = g_dis[s1], w2 = g_dis[s2], w3 = g_dis[s3];
        float4 v0 = h4[(size_t)s0 * 32 + lane];
        float4 v1 = h4[(size_t)s1 * 32 + lane];
        float4 v2 = h4[(size_t)s2 * 32 + lane];
        float4 v3 = h4[(size_t)s3 * 32 + lane];
        a0.x += w0 * v0.x; a0.y += w0 * v0.y; a0.z += w0 * v0.z; a0.w += w0 * v0.w;
        a1.x += w1 * v1.x; a1.y += w1 * v1.y; a1.z += w1 * v1.z; a1.w += w1 * v1.w;
        a2.x += w2 * v2.x; a2.y += w2 * v2.y; a2.z += w2 * v2.z; a2.w += w2 * v2.w;
        a3.x += w3 * v3.x; a3.y += w3 * v3.y; a3.z += w3 * v3.z; a3.w += w3 * v3.w;
    }
    for (; e < b1; e++) {
        int s0 = g_csr[e];
        float w0 = g_dis[s0];
        float4 v0 = h4[(size_t)s0 * 32 + lane];
        a0.x += w0 * v0.x; a0.y += w0 * v0.y; a0.z += w0 * v0.z; a0.w += w0 * v0.w;
    }

    a0.x += a1.x + a2.x + a3.x;
    a0.y += a1.y + a2.y + a3.y;
    a0.z += a1.z + a2.z + a3.z;
    a0.w += a1.w + a2.w + a3.w;

    float dv = g_dis[v];
    float d2 = dv * dv;
    float4 hv = h4[(size_t)v * 32 + lane];
    float4 bv = ((const float4*)bias)[lane];

    float4 o;
    o.x = dv * a0.x + d2 * hv.x + bv.x;
    o.y = dv * a0.y + d2 * hv.y + bv.y;
    o.z = dv * a0.z + d2 * hv.z + bv.z;
    o.w = dv * a0.w + d2 * hv.w + bv.w;
    if (doRelu) {
        o.x = fmaxf(o.x, 0.f); o.y = fmaxf(o.y, 0.f);
        o.z = fmaxf(o.z, 0.f); o.w = fmaxf(o.w, 0.f);
    }
    ((float4*)out)[(size_t)v * 32 + lane] = o;
}

// ---------------- launch ----------------

extern "C" void kernel_launch(void* const* d_in, const int* in_sizes, int n_in,
                              void* d_out, int out_size)
{
    const int*   eidx = (const int*)d_in[0];
    const float* emb  = (const float*)d_in[2];
    const float* W1   = (const float*)d_in[3];
    const float* b1   = (const float*)d_in[4];
    const float* W2   = (const float*)d_in[5];
    const float* b2   = (const float*)d_in[6];
    float* out = (float*)d_out;

    const int E = in_sizes[0] / 2;
    const int N = in_sizes[2] / FDIM;
    const int* src = eidx;
    const int* dst = eidx + E;

    const int GEMM_SMEM = (128 * 128 + 64 * 129) * (int)sizeof(float);  // 98560 B
    cudaFuncSetAttribute(k_gemm, cudaFuncAttributeMaxDynamicSharedMemorySize, GEMM_SMEM);

    float* hbuf; cudaGetSymbolAddress((void**)&hbuf, g_h);
    float* abuf; cudaGetSymbolAddress((void**)&abuf, g_agg);

    const int nb = (N + 255) / 256;
    const int eb = (E + 255) / 256;
    const int scanBlocks = (N + SCAN_B - 1) / SCAN_B;
    const int gemmBlocks = (N + 63) / 64;
    const int aggBlocks = (N * 32 + 255) / 256;  // 1 warp/node

    // CSR build (by dst) + norms
    k_zero_deg<<<nb, 256>>>(N);
    k_count<<<eb, 256>>>(dst, E);
    k_dis<<<nb, 256>>>(N);
    k_blocksum<<<scanBlocks, SCAN_B>>>(N);
    k_scanbsums<<<1, 1024>>>(scanBlocks, N);
    k_rowptr<<<scanBlocks, SCAN_B>>>(N);
    k_fill<<<eb, 256>>>(src, dst, E);

    // ---- layer 1 ----
    k_gemm<<<gemmBlocks, 256, GEMM_SMEM>>>(emb, W1, hbuf, N);
    k_aggregate<<<aggBlocks, 256>>>(hbuf, b1, abuf, N, 1);

    // ---- layer 2 ----
    k_gemm<<<gemmBlocks, 256, GEMM_SMEM>>>(abuf, W2, hbuf, N);
    k_aggregate<<<aggBlocks, 256>>>(hbuf, b2, out, N, 0);
}

// round 5
// speedup vs baseline: 1.8103x; 1.0047x over previous
#include <cuda_runtime.h>
#include <cuda_bf16.h>

#define MAX_NODES 100000
#define MAX_EDGES 1600000
#define FDIM 128
#define SCAN_B 256
#define MAX_BLOCKS ((MAX_NODES + SCAN_B - 1) / SCAN_B)   // 391

// Scratch (allocation-free rule: __device__ globals)
__device__ int   g_deg[MAX_NODES];
__device__ float g_dis[MAX_NODES];
__device__ int   g_rowptr[MAX_NODES + 1];
__device__ int   g_fill[MAX_NODES];
__device__ int   g_bsum[MAX_BLOCKS];
__device__ int   g_csr[MAX_EDGES];                 // src ids sorted by dst
__device__ float g_h[(size_t)MAX_NODES * FDIM];    // 51.2 MB
__device__ float g_agg[(size_t)MAX_NODES * FDIM];  // 51.2 MB

// ---------------- CSR build ----------------

__global__ void k_zero_deg(int n) {
    int i = blockIdx.x * blockDim.x + threadIdx.x;
    if (i < n) g_deg[i] = 0;
}

__global__ void k_count(const int* __restrict__ dst, int E) {
    int i = blockIdx.x * blockDim.x + threadIdx.x;
    if (i < E) atomicAdd(&g_deg[dst[i]], 1);
}

__global__ void k_dis(int n) {
    int i = blockIdx.x * blockDim.x + threadIdx.x;
    if (i < n) g_dis[i] = rsqrtf((float)(g_deg[i] + 1));  // +1 self-loop
}

// Phase 1: per-block sum of degrees
__global__ void k_blocksum(int N) {
    __shared__ int s[SCAN_B];
    int i = blockIdx.x * SCAN_B + threadIdx.x;
    s[threadIdx.x] = (i < N) ? g_deg[i] : 0;
    __syncthreads();
#pragma unroll
    for (int off = SCAN_B / 2; off > 0; off >>= 1) {
        if (threadIdx.x < off) s[threadIdx.x] += s[threadIdx.x + off];
        __syncthreads();
    }
    if (threadIdx.x == 0) g_bsum[blockIdx.x] = s[0];
}

// Phase 2: single-block exclusive scan of block sums (nb <= 1024)
__global__ void k_scanbsums(int nb, int N) {
    __shared__ int s[1024];
    int t = threadIdx.x;
    int v = (t < nb) ? g_bsum[t] : 0;
    s[t] = v;
    __syncthreads();
    for (int off = 1; off < 1024; off <<= 1) {
        int u = (t >= off) ? s[t - off] : 0;
        __syncthreads();
        s[t] += u;
        __syncthreads();
    }
    if (t < nb) g_bsum[t] = s[t] - v;          // exclusive
    if (t == nb - 1) g_rowptr[N] = s[t];       // total edge count
}

// Phase 3: block-local exclusive scan + block offset -> rowptr/fill
__global__ void k_rowptr(int N) {
    __shared__ int s[SCAN_B];
    int i = blockIdx.x * SCAN_B + threadIdx.x;
    int t = threadIdx.x;
    int d = (i < N) ? g_deg[i] : 0;
    s[t] = d;
    __syncthreads();
#pragma unroll
    for (int off = 1; off < SCAN_B; off <<= 1) {
        int u = (t >= off) ? s[t - off] : 0;
        __syncthreads();
        s[t] += u;
        __syncthreads();
    }
    if (i < N) {
        int p = g_bsum[blockIdx.x] + s[t] - d;  // exclusive position
        g_rowptr[i] = p;
        g_fill[i]   = p;
    }
}

__global__ void k_fill(const int* __restrict__ src, const int* __restrict__ dst, int E) {
    int i = blockIdx.x * blockDim.x + threadIdx.x;
    if (i < E) {
        int p = atomicAdd(&g_fill[dst[i]], 1);
        g_csr[p] = src[i];
    }
}

// ---------------- GEMM: H[N,128] = X[N,128] @ W[128,128] ----------------

__global__ void k_gemm(const float* __restrict__ X, const float* __restrict__ W,
                       float* __restrict__ H, int N)
{
    extern __shared__ float sm[];
    float* Ws = sm;              // 128*128
    float* Xs = sm + 128 * 128;  // 64*129 padded

    int t = threadIdx.x;
    int row0 = blockIdx.x * 64;
    int rows = N - row0; if (rows > 64) rows = 64;

    const float4* W4 = (const float4*)W;
    float4* Ws4 = (float4*)Ws;
#pragma unroll
    for (int i = 0; i < 16; i++) Ws4[t + i * 256] = W4[t + i * 256];

    for (int i = t; i < 64 * 32; i += 256) {
        int r = i >> 5, c = i & 31;
        float4 v = (r < rows) ? ((const float4*)(X + (size_t)(row0 + r) * FDIM))[c]
                              : make_float4(0.f, 0.f, 0.f, 0.f);
        float* dp = Xs + r * 129 + c * 4;
        dp[0] = v.x; dp[1] = v.y; dp[2] = v.z; dp[3] = v.w;
    }
    __syncthreads();

    int tn = (t & 31) * 4;
    int tm = (t >> 5) * 8;

    float acc[8][4];
#pragma unroll
    for (int i = 0; i < 8; i++)
#pragma unroll
        for (int j = 0; j < 4; j++) acc[i][j] = 0.f;

#pragma unroll 4
    for (int k = 0; k < 128; k++) {
        float4 b = *(const float4*)(Ws + k * 128 + tn);
#pragma unroll
        for (int i = 0; i < 8; i++) {
            float a = Xs[(tm + i) * 129 + k];
            acc[i][0] += a * b.x;
            acc[i][1] += a * b.y;
            acc[i][2] += a * b.z;
            acc[i][3] += a * b.w;
        }
    }

#pragma unroll
    for (int i = 0; i < 8; i++) {
        int r = tm + i;
        if (r < rows)
            *(float4*)(H + (size_t)(row0 + r) * FDIM + tn) =
                make_float4(acc[i][0], acc[i][1], acc[i][2], acc[i][3]);
    }
}

// ---------------- CSR aggregate + fused epilogue ----------------
// One warp per dst node; each lane owns one float4 (4 features).
// out[v] = act( dis[v] * sum_{s in N(v)} dis[s]*h[s]  +  dis[v]^2 * h[v]  +  b )

__global__ void k_aggregate(const float* __restrict__ h, const float* __restrict__ bias,
                            float* __restrict__ out, int N, int doRelu)
{
    int lane = threadIdx.x & 31;
    int v = (blockIdx.x * blockDim.x + threadIdx.x) >> 5;
    if (v >= N) return;

    int b0 = g_rowptr[v];
    int b1 = g_rowptr[v + 1];
    const float4* h4 = (const float4*)h;

    float4 a0 = make_float4(0.f, 0.f, 0.f, 0.f);
    float4 a1 = a0, a2 = a0, a3 = a0;

    int e = b0;
    for (; e + 4 <= b1; e += 4) {
        int s0 = g_csr[e], s1 = g_csr[e + 1], s2 = g_csr[e + 2], s3 = g_csr[e + 3];
        float w0 = g_dis[s0], w1 = g_dis[s1], w2 = g_dis[s2], w3 = g_dis[s3];
        float4 v0 = h4[(size_t)s0 * 32 + lane];
        float4 v1 = h4[(size_t)s1 * 32 + lane];
        float4 v2 = h4[(size_t)s2 * 32 + lane];
        float4 v3 = h4[(size_t)s3 * 32 + lane];
        a0.x += w0 * v0.x; a0.y += w0 * v0.y; a0.z += w0 * v0.z; a0.w += w0 * v0.w;
        a1.x += w1 * v1.x; a1.y += w1 * v1.y; a1.z += w1 * v1.z; a1.w += w1 * v1.w;
        a2.x += w2 * v2.x; a2.y += w2 * v2.y; a2.z += w2 * v2.z; a2.w += w2 * v2.w;
        a3.x += w3 * v3.x; a3.y += w3 * v3.y; a3.z += w3 * v3.z; a3.w += w3 * v3.w;
    }
    for (; e < b1; e++) {
        int s0 = g_csr[e];
        float w0 = g_dis[s0];
        float4 v0 = h4[(size_t)s0 * 32 + lane];
        a0.x += w0 * v0.x; a0.y += w0 * v0.y; a0.z += w0 * v0.z; a0.w += w0 * v0.w;
    }

    a0.x += a1.x + a2.x + a3.x;
    a0.y += a1.y + a2.y + a3.y;
    a0.z += a1.z + a2.z + a3.z;
    a0.w += a1.w + a2.w + a3.w;

    float dv = g_dis[v];
    float d2 = dv * dv;
    float4 hv = h4[(size_t)v * 32 + lane];
    float4 bv = ((const float4*)bias)[lane];

    float4 o;
    o.x = dv * a0.x + d2 * hv.x + bv.x;
    o.y = dv * a0.y + d2 * hv.y + bv.y;
    o.z = dv * a0.z + d2 * hv.z + bv.z;
    o.w = dv * a0.w + d2 * hv.w + bv.w;
    if (doRelu) {
        o.x = fmaxf(o.x, 0.f); o.y = fmaxf(o.y, 0.f);
        o.z = fmaxf(o.z, 0.f); o.w = fmaxf(o.w, 0.f);
    }
    ((float4*)out)[(size_t)v * 32 + lane] = o;
}

// ---------------- launch ----------------

extern "C" void kernel_launch(void* const* d_in, const int* in_sizes, int n_in,
                              void* d_out, int out_size)
{
    const int*   eidx = (const int*)d_in[0];
    const float* emb  = (const float*)d_in[2];
    const float* W1   = (const float*)d_in[3];
    const float* b1   = (const float*)d_in[4];
    const float* W2   = (const float*)d_in[5];
    const float* b2   = (const float*)d_in[6];
    float* out = (float*)d_out;

    const int E = in_sizes[0] / 2;
    const int N = in_sizes[2] / FDIM;
    const int* src = eidx;
    const int* dst = eidx + E;

    const int GEMM_SMEM = (128 * 128 + 64 * 129) * (int)sizeof(float);  // 98560 B
    cudaFuncSetAttribute(k_gemm, cudaFuncAttributeMaxDynamicSharedMemorySize, GEMM_SMEM);

    float* hbuf; cudaGetSymbolAddress((void**)&hbuf, g_h);
    float* abuf; cudaGetSymbolAddress((void**)&abuf, g_agg);

    const int nb = (N + 255) / 256;
    const int eb = (E + 255) / 256;
    const int scanBlocks = (N + SCAN_B - 1) / SCAN_B;
    const int gemmBlocks = (N + 63) / 64;
    const int aggBlocks = (N * 32 + 255) / 256;  // 1 warp/node

    // CSR build (by dst) + norms
    k_zero_deg<<<nb, 256>>>(N);
    k_count<<<eb, 256>>>(dst, E);
    k_dis<<<nb, 256>>>(N);
    k_blocksum<<<scanBlocks, SCAN_B>>>(N);
    k_scanbsums<<<1, 1024>>>(scanBlocks, N);
    k_rowptr<<<scanBlocks, SCAN_B>>>(N);
    k_fill<<<eb, 256>>>(src, dst, E);

    // ---- layer 1 ----
    k_gemm<<<gemmBlocks, 256, GEMM_SMEM>>>(emb, W1, hbuf, N);
    k_aggregate<<<aggBlocks, 256>>>(hbuf, b1, abuf, N, 1);

    // ---- layer 2 ----
    k_gemm<<<gemmBlocks, 256, GEMM_SMEM>>>(abuf, W2, hbuf, N);
    k_aggregate<<<aggBlocks, 256>>>(hbuf, b2, out, N, 0);
}

// round 6
// speedup vs baseline: 1.9431x; 1.0734x over previous
#include <cuda_runtime.h>
#include <cuda_fp16.h>

#define MAX_NODES 100000
#define MAX_EDGES 1600000
#define FDIM 128
#define SCAN_B 256
#define MAX_BLOCKS ((MAX_NODES + SCAN_B - 1) / SCAN_B)   // 391

// Scratch (allocation-free rule: __device__ globals)
__device__ int    g_deg[MAX_NODES];
__device__ float  g_dis[MAX_NODES];
__device__ int    g_rowptr[MAX_NODES + 1];
__device__ int    g_fill[MAX_NODES];
__device__ int    g_bsum[MAX_BLOCKS];
__device__ int    g_csr[MAX_EDGES];                  // src ids sorted by dst
__device__ __half g_hb[(size_t)MAX_NODES * FDIM];    // 25.6 MB: dis-scaled features, fp16
__device__ float  g_agg[(size_t)MAX_NODES * FDIM];   // 51.2 MB: fp32 layer-1 output

// ---------------- CSR build ----------------

__global__ void k_zero_deg(int n) {
    int i = blockIdx.x * blockDim.x + threadIdx.x;
    if (i < n) g_deg[i] = 0;
}

__global__ void k_count(const int* __restrict__ dst, int E) {
    int i = blockIdx.x * blockDim.x + threadIdx.x;
    if (i < E) atomicAdd(&g_deg[dst[i]], 1);
}

__global__ void k_dis(int n) {
    int i = blockIdx.x * blockDim.x + threadIdx.x;
    if (i < n) g_dis[i] = rsqrtf((float)(g_deg[i] + 1));  // +1 self-loop
}

__global__ void k_blocksum(int N) {
    __shared__ int s[SCAN_B];
    int i = blockIdx.x * SCAN_B + threadIdx.x;
    s[threadIdx.x] = (i < N) ? g_deg[i] : 0;
    __syncthreads();
#pragma unroll
    for (int off = SCAN_B / 2; off > 0; off >>= 1) {
        if (threadIdx.x < off) s[threadIdx.x] += s[threadIdx.x + off];
        __syncthreads();
    }
    if (threadIdx.x == 0) g_bsum[blockIdx.x] = s[0];
}

__global__ void k_scanbsums(int nb, int N) {
    __shared__ int s[1024];
    int t = threadIdx.x;
    int v = (t < nb) ? g_bsum[t] : 0;
    s[t] = v;
    __syncthreads();
    for (int off = 1; off < 1024; off <<= 1) {
        int u = (t >= off) ? s[t - off] : 0;
        __syncthreads();
        s[t] += u;
        __syncthreads();
    }
    if (t < nb) g_bsum[t] = s[t] - v;
    if (t == nb - 1) g_rowptr[N] = s[t];
}

__global__ void k_rowptr(int N) {
    __shared__ int s[SCAN_B];
    int i = blockIdx.x * SCAN_B + threadIdx.x;
    int t = threadIdx.x;
    int d = (i < N) ? g_deg[i] : 0;
    s[t] = d;
    __syncthreads();
#pragma unroll
    for (int off = 1; off < SCAN_B; off <<= 1) {
        int u = (t >= off) ? s[t - off] : 0;
        __syncthreads();
        s[t] += u;
        __syncthreads();
    }
    if (i < N) {
        int p = g_bsum[blockIdx.x] + s[t] - d;
        g_rowptr[i] = p;
        g_fill[i]   = p;
    }
}

__global__ void k_fill(const int* __restrict__ src, const int* __restrict__ dst, int E) {
    int i = blockIdx.x * blockDim.x + threadIdx.x;
    if (i < E) {
        int p = atomicAdd(&g_fill[dst[i]], 1);
        g_csr[p] = src[i];
    }
}

// ---------------- GEMM: Hb[r,:] = fp16( dis[r] * (X[r,:] @ W) ) ----------------

__global__ void k_gemm(const float* __restrict__ X, const float* __restrict__ W,
                       __half* __restrict__ H, int N)
{
    extern __shared__ float sm[];
    float* Ws = sm;              // 128*128
    float* Xs = sm + 128 * 128;  // 64*129 padded

    int t = threadIdx.x;
    int row0 = blockIdx.x * 64;
    int rows = N - row0; if (rows > 64) rows = 64;

    const float4* W4 = (const float4*)W;
    float4* Ws4 = (float4*)Ws;
#pragma unroll
    for (int i = 0; i < 16; i++) Ws4[t + i * 256] = W4[t + i * 256];

    for (int i = t; i < 64 * 32; i += 256) {
        int r = i >> 5, c = i & 31;
        float4 v = (r < rows) ? ((const float4*)(X + (size_t)(row0 + r) * FDIM))[c]
                              : make_float4(0.f, 0.f, 0.f, 0.f);
        float* dp = Xs + r * 129 + c * 4;
        dp[0] = v.x; dp[1] = v.y; dp[2] = v.z; dp[3] = v.w;
    }
    __syncthreads();

    int tn = (t & 31) * 4;
    int tm = (t >> 5) * 8;

    float acc[8][4];
#pragma unroll
    for (int i = 0; i < 8; i++)
#pragma unroll
        for (int j = 0; j < 4; j++) acc[i][j] = 0.f;

#pragma unroll 4
    for (int k = 0; k < 128; k++) {
        float4 b = *(const float4*)(Ws + k * 128 + tn);
#pragma unroll
        for (int i = 0; i < 8; i++) {
            float a = Xs[(tm + i) * 129 + k];
            acc[i][0] += a * b.x;
            acc[i][1] += a * b.y;
            acc[i][2] += a * b.z;
            acc[i][3] += a * b.w;
        }
    }

#pragma unroll
    for (int i = 0; i < 8; i++) {
        int r = tm + i;
        if (r < rows) {
            float s = g_dis[row0 + r];
            __half2 p0 = __floats2half2_rn(acc[i][0] * s, acc[i][1] * s);
            __half2 p1 = __floats2half2_rn(acc[i][2] * s, acc[i][3] * s);
            uint2 u;
            u.x = *(unsigned*)&p0;
            u.y = *(unsigned*)&p1;
            *(uint2*)(H + (size_t)(row0 + r) * FDIM + tn) = u;
        }
    }
}

// ---------------- CSR aggregate + fused epilogue ----------------
// One warp per dst node; lane owns 4 features (8 B fp16 per gather).
// out[v] = act( dis[v] * ( sum_{s in N(v)} hs[s] + hs[v] ) + b ),  hs = dis.*h

__global__ void k_aggregate(const __half* __restrict__ h, const float* __restrict__ bias,
                            float* __restrict__ out, int N, int doRelu)
{
    int lane = threadIdx.x & 31;
    int v = (blockIdx.x * blockDim.x + threadIdx.x) >> 5;
    if (v >= N) return;

    int b0 = g_rowptr[v];
    int b1 = g_rowptr[v + 1];
    const uint2* h2 = (const uint2*)h;   // 32 uint2 per row (128 halves)

    float4 a0 = make_float4(0.f, 0.f, 0.f, 0.f);
    float4 a1 = a0, a2 = a0, a3 = a0;

    int e = b0;
    for (; e + 4 <= b1; e += 4) {
        int s0 = g_csr[e], s1 = g_csr[e + 1], s2 = g_csr[e + 2], s3 = g_csr[e + 3];
        uint2 u0 = h2[(size_t)s0 * 32 + lane];
        uint2 u1 = h2[(size_t)s1 * 32 + lane];
        uint2 u2 = h2[(size_t)s2 * 32 + lane];
        uint2 u3 = h2[(size_t)s3 * 32 + lane];
        float2 f;
        f = __half22float2(*(__half2*)&u0.x); a0.x += f.x; a0.y += f.y;
        f = __half22float2(*(__half2*)&u0.y); a0.z += f.x; a0.w += f.y;
        f = __half22float2(*(__half2*)&u1.x); a1.x += f.x; a1.y += f.y;
        f = __half22float2(*(__half2*)&u1.y); a1.z += f.x; a1.w += f.y;
        f = __half22float2(*(__half2*)&u2.x); a2.x += f.x; a2.y += f.y;
        f = __half22float2(*(__half2*)&u2.y); a2.z += f.x; a2.w += f.y;
        f = __half22float2(*(__half2*)&u3.x); a3.x += f.x; a3.y += f.y;
        f = __half22float2(*(__half2*)&u3.y); a3.z += f.x; a3.w += f.y;
    }
    for (; e < b1; e++) {
        int s0 = g_csr[e];
        uint2 u0 = h2[(size_t)s0 * 32 + lane];
        float2 f;
        f = __half22float2(*(__half2*)&u0.x); a0.x += f.x; a0.y += f.y;
        f = __half22float2(*(__half2*)&u0.y); a0.z += f.x; a0.w += f.y;
    }

    // self-loop term: + hs[v]
    {
        uint2 uv = h2[(size_t)v * 32 + lane];
        float2 f;
        f = __half22float2(*(__half2*)&uv.x); a1.x += f.x; a1.y += f.y;
        f = __half22float2(*(__half2*)&uv.y); a1.z += f.x; a1.w += f.y;
    }

    a0.x += a1.x + a2.x + a3.x;
    a0.y += a1.y + a2.y + a3.y;
    a0.z += a1.z + a2.z + a3.z;
    a0.w += a1.w + a2.w + a3.w;

    float dv = g_dis[v];
    float4 bv = ((const float4*)bias)[lane];

    float4 o;
    o.x = dv * a0.x + bv.x;
    o.y = dv * a0.y + bv.y;
    o.z = dv * a0.z + bv.z;
    o.w = dv * a0.w + bv.w;
    if (doRelu) {
        o.x = fmaxf(o.x, 0.f); o.y = fmaxf(o.y, 0.f);
        o.z = fmaxf(o.z, 0.f); o.w = fmaxf(o.w, 0.f);
    }
    ((float4*)out)[(size_t)v * 32 + lane] = o;
}

// ---------------- launch ----------------

extern "C" void kernel_launch(void* const* d_in, const int* in_sizes, int n_in,
                              void* d_out, int out_size)
{
    const int*   eidx = (const int*)d_in[0];
    const float* emb  = (const float*)d_in[2];
    const float* W1   = (const float*)d_in[3];
    const float* b1   = (const float*)d_in[4];
    const float* W2   = (const float*)d_in[5];
    const float* b2   = (const float*)d_in[6];
    float* out = (float*)d_out;

    const int E = in_sizes[0] / 2;
    const int N = in_sizes[2] / FDIM;
    const int* src = eidx;
    const int* dst = eidx + E;

    const int GEMM_SMEM = (128 * 128 + 64 * 129) * (int)sizeof(float);  // 98560 B
    cudaFuncSetAttribute(k_gemm, cudaFuncAttributeMaxDynamicSharedMemorySize, GEMM_SMEM);

    __half* hbuf; cudaGetSymbolAddress((void**)&hbuf, g_hb);
    float*  abuf; cudaGetSymbolAddress((void**)&abuf, g_agg);

    const int nb = (N + 255) / 256;
    const int eb = (E + 255) / 256;
    const int scanBlocks = (N + SCAN_B - 1) / SCAN_B;
    const int gemmBlocks = (N + 63) / 64;
    const int aggBlocks = (N * 32 + 255) / 256;  // 1 warp/node

    // CSR build (by dst) + norms
    k_zero_deg<<<nb, 256>>>(N);
    k_count<<<eb, 256>>>(dst, E);
    k_dis<<<nb, 256>>>(N);
    k_blocksum<<<scanBlocks, SCAN_B>>>(N);
    k_scanbsums<<<1, 1024>>>(scanBlocks, N);
    k_rowptr<<<scanBlocks, SCAN_B>>>(N);
    k_fill<<<eb, 256>>>(src, dst, E);

    // ---- layer 1 ----
    k_gemm<<<gemmBlocks, 256, GEMM_SMEM>>>(emb, W1, hbuf, N);
    k_aggregate<<<aggBlocks, 256>>>(hbuf, b1, abuf, N, 1);

    // ---- layer 2 ----
    k_gemm<<<gemmBlocks, 256, GEMM_SMEM>>>(abuf, W2, hbuf, N);
    k_aggregate<<<aggBlocks, 256>>>(hbuf, b2, out, N, 0);
}

// round 7
// speedup vs baseline: 1.9444x; 1.0007x over previous
#include <cuda_runtime.h>
#include <cuda_fp16.h>

#define MAX_NODES 100000
#define MAX_EDGES 1600000
#define FDIM 128
#define SCAN_B 256
#define MAX_BLOCKS ((MAX_NODES + SCAN_B - 1) / SCAN_B)   // 391

// Scratch (allocation-free rule: __device__ globals)
__device__ int    g_deg[MAX_NODES];
__device__ float  g_dis[MAX_NODES];
__device__ int    g_rowptr[MAX_NODES + 1];
__device__ int    g_fill[MAX_NODES];
__device__ int    g_bsum[MAX_BLOCKS];
__device__ int    g_csr[MAX_EDGES];                  // src ids sorted by dst
__device__ __half g_hb[(size_t)MAX_NODES * FDIM];    // 25.6 MB: dis-scaled features, fp16
__device__ float  g_agg[(size_t)MAX_NODES * FDIM];   // 51.2 MB: fp32 layer-1 output

// ---------------- CSR build ----------------

__global__ void k_zero_deg(int n) {
    int i = blockIdx.x * blockDim.x + threadIdx.x;
    if (i < n) g_deg[i] = 0;
}

__global__ void k_count(const int* __restrict__ dst, int E) {
    int i = blockIdx.x * blockDim.x + threadIdx.x;
    if (i < E) atomicAdd(&g_deg[dst[i]], 1);
}

__global__ void k_dis(int n) {
    int i = blockIdx.x * blockDim.x + threadIdx.x;
    if (i < n) g_dis[i] = rsqrtf((float)(g_deg[i] + 1));  // +1 self-loop
}

__global__ void k_blocksum(int N) {
    __shared__ int s[SCAN_B];
    int i = blockIdx.x * SCAN_B + threadIdx.x;
    s[threadIdx.x] = (i < N) ? g_deg[i] : 0;
    __syncthreads();
#pragma unroll
    for (int off = SCAN_B / 2; off > 0; off >>= 1) {
        if (threadIdx.x < off) s[threadIdx.x] += s[threadIdx.x + off];
        __syncthreads();
    }
    if (threadIdx.x == 0) g_bsum[blockIdx.x] = s[0];
}

__global__ void k_scanbsums(int nb, int N) {
    __shared__ int s[1024];
    int t = threadIdx.x;
    int v = (t < nb) ? g_bsum[t] : 0;
    s[t] = v;
    __syncthreads();
    for (int off = 1; off < 1024; off <<= 1) {
        int u = (t >= off) ? s[t - off] : 0;
        __syncthreads();
        s[t] += u;
        __syncthreads();
    }
    if (t < nb) g_bsum[t] = s[t] - v;
    if (t == nb - 1) g_rowptr[N] = s[t];
}

__global__ void k_rowptr(int N) {
    __shared__ int s[SCAN_B];
    int i = blockIdx.x * SCAN_B + threadIdx.x;
    int t = threadIdx.x;
    int d = (i < N) ? g_deg[i] : 0;
    s[t] = d;
    __syncthreads();
#pragma unroll
    for (int off = 1; off < SCAN_B; off <<= 1) {
        int u = (t >= off) ? s[t - off] : 0;
        __syncthreads();
        s[t] += u;
        __syncthreads();
    }
    if (i < N) {
        int p = g_bsum[blockIdx.x] + s[t] - d;
        g_rowptr[i] = p;
        g_fill[i]   = p;
    }
}

__global__ void k_fill(const int* __restrict__ src, const int* __restrict__ dst, int E) {
    int i = blockIdx.x * blockDim.x + threadIdx.x;
    if (i < E) {
        int p = atomicAdd(&g_fill[dst[i]], 1);
        g_csr[p] = src[i];
    }
}

// ---------------- GEMM: Hb[r,:] = fp16( dis[r] * (X[r,:] @ W) ) ----------------

__global__ void k_gemm(const float* __restrict__ X, const float* __restrict__ W,
                       __half* __restrict__ H, int N)
{
    extern __shared__ float sm[];
    float* Ws = sm;              // 128*128
    float* Xs = sm + 128 * 128;  // 64*129 padded

    int t = threadIdx.x;
    int row0 = blockIdx.x * 64;
    int rows = N - row0; if (rows > 64) rows = 64;

    const float4* W4 = (const float4*)W;
    float4* Ws4 = (float4*)Ws;
#pragma unroll
    for (int i = 0; i < 16; i++) Ws4[t + i * 256] = W4[t + i * 256];

    for (int i = t; i < 64 * 32; i += 256) {
        int r = i >> 5, c = i & 31;
        float4 v = (r < rows) ? ((const float4*)(X + (size_t)(row0 + r) * FDIM))[c]
                              : make_float4(0.f, 0.f, 0.f, 0.f);
        float* dp = Xs + r * 129 + c * 4;
        dp[0] = v.x; dp[1] = v.y; dp[2] = v.z; dp[3] = v.w;
    }
    __syncthreads();

    int tn = (t & 31) * 4;
    int tm = (t >> 5) * 8;

    float acc[8][4];
#pragma unroll
    for (int i = 0; i < 8; i++)
#pragma unroll
        for (int j = 0; j < 4; j++) acc[i][j] = 0.f;

#pragma unroll 4
    for (int k = 0; k < 128; k++) {
        float4 b = *(const float4*)(Ws + k * 128 + tn);
#pragma unroll
        for (int i = 0; i < 8; i++) {
            float a = Xs[(tm + i) * 129 + k];
            acc[i][0] += a * b.x;
            acc[i][1] += a * b.y;
            acc[i][2] += a * b.z;
            acc[i][3] += a * b.w;
        }
    }

#pragma unroll
    for (int i = 0; i < 8; i++) {
        int r = tm + i;
        if (r < rows) {
            float s = g_dis[row0 + r];
            __half2 p0 = __floats2half2_rn(acc[i][0] * s, acc[i][1] * s);
            __half2 p1 = __floats2half2_rn(acc[i][2] * s, acc[i][3] * s);
            uint2 u;
            u.x = *(unsigned*)&p0;
            u.y = *(unsigned*)&p1;
            *(uint2*)(H + (size_t)(row0 + r) * FDIM + tn) = u;
        }
    }
}

// ---------------- CSR aggregate + fused epilogue ----------------
// One warp per dst node; lane owns 4 features (8 B fp16 per gather).
// out[v] = act( dis[v] * ( sum_{s in N(v)} hs[s] + hs[v] ) + b ),  hs = dis.*h

__global__ void k_aggregate(const __half* __restrict__ h, const float* __restrict__ bias,
                            float* __restrict__ out, int N, int doRelu)
{
    int lane = threadIdx.x & 31;
    int v = (blockIdx.x * blockDim.x + threadIdx.x) >> 5;
    if (v >= N) return;

    int b0 = g_rowptr[v];
    int b1 = g_rowptr[v + 1];
    const uint2* h2 = (const uint2*)h;   // 32 uint2 per row (128 halves)

    float4 a0 = make_float4(0.f, 0.f, 0.f, 0.f);
    float4 a1 = a0, a2 = a0, a3 = a0;

    int e = b0;
    for (; e + 4 <= b1; e += 4) {
        int s0 = g_csr[e], s1 = g_csr[e + 1], s2 = g_csr[e + 2], s3 = g_csr[e + 3];
        uint2 u0 = h2[(size_t)s0 * 32 + lane];
        uint2 u1 = h2[(size_t)s1 * 32 + lane];
        uint2 u2 = h2[(size_t)s2 * 32 + lane];
        uint2 u3 = h2[(size_t)s3 * 32 + lane];
        float2 f;
        f = __half22float2(*(__half2*)&u0.x); a0.x += f.x; a0.y += f.y;
        f = __half22float2(*(__half2*)&u0.y); a0.z += f.x; a0.w += f.y;
        f = __half22float2(*(__half2*)&u1.x); a1.x += f.x; a1.y += f.y;
        f = __half22float2(*(__half2*)&u1.y); a1.z += f.x; a1.w += f.y;
        f = __half22float2(*(__half2*)&u2.x); a2.x += f.x; a2.y += f.y;
        f = __half22float2(*(__half2*)&u2.y); a2.z += f.x; a2.w += f.y;
        f = __half22float2(*(__half2*)&u3.x); a3.x += f.x; a3.y += f.y;
        f = __half22float2(*(__half2*)&u3.y); a3.z += f.x; a3.w += f.y;
    }
    for (; e < b1; e++) {
        int s0 = g_csr[e];
        uint2 u0 = h2[(size_t)s0 * 32 + lane];
        float2 f;
        f = __half22float2(*(__half2*)&u0.x); a0.x += f.x; a0.y += f.y;
        f = __half22float2(*(__half2*)&u0.y); a0.z += f.x; a0.w += f.y;
    }

    // self-loop term: + hs[v]
    {
        uint2 uv = h2[(size_t)v * 32 + lane];
        float2 f;
        f = __half22float2(*(__half2*)&uv.x); a1.x += f.x; a1.y += f.y;
        f = __half22float2(*(__half2*)&uv.y); a1.z += f.x; a1.w += f.y;
    }

    a0.x += a1.x + a2.x + a3.x;
    a0.y += a1.y + a2.y + a3.y;
    a0.z += a1.z + a2.z + a3.z;
    a0.w += a1.w + a2.w + a3.w;

    float dv = g_dis[v];
    float4 bv = ((const float4*)bias)[lane];

    float4 o;
    o.x = dv * a0.x + bv.x;
    o.y = dv * a0.y + bv.y;
    o.z = dv * a0.z + bv.z;
    o.w = dv * a0.w + bv.w;
    if (doRelu) {
        o.x = fmaxf(o.x, 0.f); o.y = fmaxf(o.y, 0.f);
        o.z = fmaxf(o.z, 0.f); o.w = fmaxf(o.w, 0.f);
    }
    ((float4*)out)[(size_t)v * 32 + lane] = o;
}

// ---------------- launch ----------------

extern "C" void kernel_launch(void* const* d_in, const int* in_sizes, int n_in,
                              void* d_out, int out_size)
{
    const int*   eidx = (const int*)d_in[0];
    const float* emb  = (const float*)d_in[2];
    const float* W1   = (const float*)d_in[3];
    const float* b1   = (const float*)d_in[4];
    const float* W2   = (const float*)d_in[5];
    const float* b2   = (const float*)d_in[6];
    float* out = (float*)d_out;

    const int E = in_sizes[0] / 2;
    const int N = in_sizes[2] / FDIM;
    const int* src = eidx;
    const int* dst = eidx + E;

    const int GEMM_SMEM = (128 * 128 + 64 * 129) * (int)sizeof(float);  // 98560 B
    cudaFuncSetAttribute(k_gemm, cudaFuncAttributeMaxDynamicSharedMemorySize, GEMM_SMEM);

    __half* hbuf; cudaGetSymbolAddress((void**)&hbuf, g_hb);
    float*  abuf; cudaGetSymbolAddress((void**)&abuf, g_agg);

    const int nb = (N + 255) / 256;
    const int eb = (E + 255) / 256;
    const int scanBlocks = (N + SCAN_B - 1) / SCAN_B;
    const int gemmBlocks = (N + 63) / 64;
    const int aggBlocks = (N * 32 + 255) / 256;  // 1 warp/node

    // CSR build (by dst) + norms
    k_zero_deg<<<nb, 256>>>(N);
    k_count<<<eb, 256>>>(dst, E);
    k_dis<<<nb, 256>>>(N);
    k_blocksum<<<scanBlocks, SCAN_B>>>(N);
    k_scanbsums<<<1, 1024>>>(scanBlocks, N);
    k_rowptr<<<scanBlocks, SCAN_B>>>(N);
    k_fill<<<eb, 256>>>(src, dst, E);

    // ---- layer 1 ----
    k_gemm<<<gemmBlocks, 256, GEMM_SMEM>>>(emb, W1, hbuf, N);
    k_aggregate<<<aggBlocks, 256>>>(hbuf, b1, abuf, N, 1);

    // ---- layer 2 ----
    k_gemm<<<gemmBlocks, 256, GEMM_SMEM>>>(abuf, W2, hbuf, N);
    k_aggregate<<<aggBlocks, 256>>>(hbuf, b2, out, N, 0);
}